// round 1
// baseline (speedup 1.0000x reference)
#include <cuda_runtime.h>
#include <math.h>

#define CC   192
#define C3   576
#define NB   2
#define NHD  4
#define HD   48
#define HH   256
#define WW   256
#define HWN  65536

// Scratch (device globals — allocation-free rule)
__device__ float g_qkv1[(size_t)NB * C3 * HWN];     // after 1x1 qkv conv
__device__ float g_qkv2[(size_t)NB * C3 * HWN];     // after depthwise 3x3
__device__ float g_attout[(size_t)NB * CC * HWN];   // attention output (pre-proj)
__device__ float g_gram[NB * NHD * HD * HD];        // raw q.k^T accumulators
__device__ float g_attn[NB * NHD * HD * HD];        // softmaxed attention
__device__ float g_norms[NB * 2 * CC];              // L2 norms for q (0..191) and k (192..383)

// ---------------------------------------------------------------------------
__global__ void zero_gram_kernel() {
    int i = blockIdx.x * blockDim.x + threadIdx.x;
    if (i < NB * NHD * HD * HD) g_gram[i] = 0.f;
}

// ---------------------------------------------------------------------------
// C[M,N] = A[M,K] * B[K,N], batched over z (B and C advance by stride).
// M,K multiples of 64/16; N multiple of 64. 256 threads, 4x4 micro-tile.
#define BM 64
#define BN 64
#define BK 16
__global__ void sgemm_kernel(const float* __restrict__ A,
                             const float* __restrict__ B,
                             float* __restrict__ C,
                             int N, int K,
                             size_t strideB, size_t strideC) {
    const float* Bp = B + (size_t)blockIdx.z * strideB;
    float*       Cp = C + (size_t)blockIdx.z * strideC;

    __shared__ float As[BK][BM];
    __shared__ float Bs[BK][BN];

    int tid = threadIdx.x;
    int tx = tid & 15, ty = tid >> 4;
    int rowBase = blockIdx.y * BM;
    int colBase = blockIdx.x * BN;

    int aRow = tid >> 2;         // 0..63
    int aCol = (tid & 3) << 2;   // 0,4,8,12
    int bRow = tid >> 4;         // 0..15
    int bCol = (tid & 15) << 2;  // 0..60

    float acc[4][4] = {};

    for (int k0 = 0; k0 < K; k0 += BK) {
        float4 av = *(const float4*)(A + (size_t)(rowBase + aRow) * K + k0 + aCol);
        As[aCol + 0][aRow] = av.x;
        As[aCol + 1][aRow] = av.y;
        As[aCol + 2][aRow] = av.z;
        As[aCol + 3][aRow] = av.w;
        float4 bv = *(const float4*)(Bp + (size_t)(k0 + bRow) * N + colBase + bCol);
        *(float4*)(&Bs[bRow][bCol]) = bv;
        __syncthreads();

        #pragma unroll
        for (int k = 0; k < BK; k++) {
            float a[4], b[4];
            #pragma unroll
            for (int i = 0; i < 4; i++) a[i] = As[k][ty * 4 + i];
            #pragma unroll
            for (int j = 0; j < 4; j++) b[j] = Bs[k][tx * 4 + j];
            #pragma unroll
            for (int i = 0; i < 4; i++)
                #pragma unroll
                for (int j = 0; j < 4; j++)
                    acc[i][j] += a[i] * b[j];
        }
        __syncthreads();
    }

    #pragma unroll
    for (int i = 0; i < 4; i++) {
        float4 v = make_float4(acc[i][0], acc[i][1], acc[i][2], acc[i][3]);
        *(float4*)(Cp + (size_t)(rowBase + ty * 4 + i) * N + colBase + tx * 4) = v;
    }
}

// ---------------------------------------------------------------------------
// Depthwise 3x3, pad 1 (cross-correlation). One thread per output element.
__global__ void dwconv_kernel(const float* __restrict__ w) {
    size_t idx = (size_t)blockIdx.x * blockDim.x + threadIdx.x;
    if (idx >= (size_t)NB * C3 * HWN) return;
    int x  = (int)(idx & (WW - 1));
    int y  = (int)((idx >> 8) & (HH - 1));
    int ch = (int)((idx >> 16) % C3);           // HWN == 1<<16
    const float* wp = w + ch * 9;
    const float* in = g_qkv1 + (idx & ~(size_t)(HWN - 1));  // channel-plane base
    float s = 0.f;
    #pragma unroll
    for (int dy = 0; dy < 3; dy++) {
        int yy = y + dy - 1;
        if (yy < 0 || yy >= HH) continue;
        #pragma unroll
        for (int dx = 0; dx < 3; dx++) {
            int xx = x + dx - 1;
            if (xx < 0 || xx >= WW) continue;
            s += wp[dy * 3 + dx] * in[yy * WW + xx];
        }
    }
    g_qkv2[idx] = s;
}

// ---------------------------------------------------------------------------
// L2 norms over spatial axis for q (channels 0..191) and k (192..383), per batch.
__global__ void rownorm_kernel() {
    int r  = blockIdx.x;               // 0 .. NB*2*CC-1
    int b  = r / (2 * CC);
    int ch = r % (2 * CC);
    const float4* p = (const float4*)(g_qkv2 + ((size_t)b * C3 + ch) * HWN);
    float ss = 0.f;
    for (int i = threadIdx.x; i < HWN / 4; i += 256) {
        float4 v = p[i];
        ss += v.x * v.x + v.y * v.y + v.z * v.z + v.w * v.w;
    }
    __shared__ float red[256];
    red[threadIdx.x] = ss;
    __syncthreads();
    for (int s = 128; s > 0; s >>= 1) {
        if (threadIdx.x < s) red[threadIdx.x] += red[threadIdx.x + s];
        __syncthreads();
    }
    if (threadIdx.x == 0) g_norms[r] = fmaxf(sqrtf(red[0]), 1e-12f);
}

// ---------------------------------------------------------------------------
// Gram = q @ k^T per (b,h): [48,48], K=65536 split across blocks (atomicAdd).
#define GK 64
#define GSPAN 4096
__global__ void gram_kernel() {
    int bh = blockIdx.y;
    int b = bh >> 2, h = bh & 3;
    const float* qb = g_qkv2 + ((size_t)b * C3 + h * HD) * HWN;
    const float* kb = g_qkv2 + ((size_t)b * C3 + CC + h * HD) * HWN;

    __shared__ float qs[GK][HD + 1];
    __shared__ float ks[GK][HD + 1];

    int tid = threadIdx.x;
    int tx = tid & 15, ty = tid >> 4;
    float acc[3][3] = {};

    int n0 = blockIdx.x * GSPAN;
    for (int nc = 0; nc < GSPAN; nc += GK) {
        int nb = n0 + nc;
        for (int i = tid; i < HD * GK; i += 256) {
            int kk = i & (GK - 1);
            int c  = i >> 6;
            qs[kk][c] = qb[(size_t)c * HWN + nb + kk];
            ks[kk][c] = kb[(size_t)c * HWN + nb + kk];
        }
        __syncthreads();
        #pragma unroll 8
        for (int kk = 0; kk < GK; kk++) {
            float qv[3], kv[3];
            #pragma unroll
            for (int i = 0; i < 3; i++) qv[i] = qs[kk][ty + 16 * i];
            #pragma unroll
            for (int j = 0; j < 3; j++) kv[j] = ks[kk][tx + 16 * j];
            #pragma unroll
            for (int i = 0; i < 3; i++)
                #pragma unroll
                for (int j = 0; j < 3; j++)
                    acc[i][j] += qv[i] * kv[j];
        }
        __syncthreads();
    }
    #pragma unroll
    for (int i = 0; i < 3; i++)
        #pragma unroll
        for (int j = 0; j < 3; j++)
            atomicAdd(&g_gram[((size_t)bh * HD + ty + 16 * i) * HD + tx + 16 * j],
                      acc[i][j]);
}

// ---------------------------------------------------------------------------
// attn = softmax( gram / (|q||k|) * temperature ), one thread per (b,h,c) row.
__global__ void attn_kernel(const float* __restrict__ temp) {
    int r = blockIdx.x * blockDim.x + threadIdx.x;
    if (r >= NB * NHD * HD) return;
    int b = r / (NHD * HD);
    int h = (r / HD) % NHD;
    int c = r % HD;
    float nq = g_norms[b * 2 * CC + h * HD + c];
    const float* gr = g_gram + (size_t)((b * NHD + h) * HD + c) * HD;
    float t = temp[h];
    float a[HD];
    float mx = -1e30f;
    for (int d = 0; d < HD; d++) {
        float nk = g_norms[b * 2 * CC + CC + h * HD + d];
        float v = gr[d] / (nq * nk) * t;
        a[d] = v;
        mx = fmaxf(mx, v);
    }
    float sum = 0.f;
    for (int d = 0; d < HD; d++) { a[d] = expf(a[d] - mx); sum += a[d]; }
    float inv = 1.f / sum;
    float* o = g_attn + (size_t)((b * NHD + h) * HD + c) * HD;
    for (int d = 0; d < HD; d++) o[d] = a[d] * inv;
}

// ---------------------------------------------------------------------------
// out[b, h*48+c, n] = sum_d attn[b,h,c,d] * v[b,h,d,n]
__global__ void av_kernel() {
    int bh = blockIdx.y;
    int b = bh >> 2, h = bh & 3;
    __shared__ float sa[HD * HD];
    for (int i = threadIdx.x; i < HD * HD; i += 256)
        sa[i] = g_attn[(size_t)bh * HD * HD + i];
    __syncthreads();
    int n = blockIdx.x * 256 + threadIdx.x;
    const float* vb = g_qkv2 + ((size_t)b * C3 + 2 * CC + h * HD) * HWN + n;
    float*       ob = g_attout + ((size_t)b * CC + h * HD) * HWN + n;
    float acc[HD];
    #pragma unroll
    for (int c = 0; c < HD; c++) acc[c] = 0.f;
    #pragma unroll 4
    for (int d = 0; d < HD; d++) {
        float v = vb[(size_t)d * HWN];
        #pragma unroll
        for (int c = 0; c < HD; c++) acc[c] += sa[c * HD + d] * v;
    }
    #pragma unroll
    for (int c = 0; c < HD; c++) ob[(size_t)c * HWN] = acc[c];
}

// ---------------------------------------------------------------------------
extern "C" void kernel_launch(void* const* d_in, const int* in_sizes, int n_in,
                              void* d_out, int out_size) {
    const float* x      = (const float*)d_in[0];
    const float* qkv_w  = (const float*)d_in[1];
    const float* dw_w   = (const float*)d_in[2];
    const float* proj_w = (const float*)d_in[3];
    const float* temp   = (const float*)d_in[4];
    float* out = (float*)d_out;

    float *qkv1, *attout;
    cudaGetSymbolAddress((void**)&qkv1,   g_qkv1);
    cudaGetSymbolAddress((void**)&attout, g_attout);

    zero_gram_kernel<<<(NB * NHD * HD * HD + 255) / 256, 256>>>();

    // qkv = qkv_w @ x  : [576,192] x [192, 65536] per batch
    sgemm_kernel<<<dim3(HWN / BN, C3 / BM, NB), 256>>>(
        qkv_w, x, qkv1, HWN, CC, (size_t)CC * HWN, (size_t)C3 * HWN);

    dwconv_kernel<<<(int)(((size_t)NB * C3 * HWN) / 256), 256>>>(dw_w);

    rownorm_kernel<<<NB * 2 * CC, 256>>>();

    gram_kernel<<<dim3(HWN / GSPAN, NB * NHD), 256>>>();

    attn_kernel<<<2, 192>>>(temp);

    av_kernel<<<dim3(HWN / 256, NB * NHD), 256>>>();

    // final = proj_w @ attout : [192,192] x [192, 65536] per batch -> d_out
    sgemm_kernel<<<dim3(HWN / BN, CC / BM, NB), 256>>>(
        proj_w, attout, out, HWN, CC, (size_t)CC * HWN, (size_t)CC * HWN);
}

// round 2
// speedup vs baseline: 1.3493x; 1.3493x over previous
#include <cuda_runtime.h>
#include <math.h>
#include <stdint.h>

#define CC   192
#define C3   576
#define NB   2
#define NHD  4
#define HD   48
#define HH   256
#define WW   256
#define HWN  65536

// Scratch (device globals — allocation-free rule)
__device__ float g_qkv1[(size_t)NB * C3 * HWN];     // after 1x1 qkv conv
__device__ float g_qkv2[(size_t)NB * C3 * HWN];     // after depthwise 3x3
__device__ float g_attout[(size_t)NB * CC * HWN];   // attention output (pre-proj)
__device__ float g_gram[NB * NHD * HD * HD];        // raw q.k^T accumulators
__device__ float g_attn[NB * NHD * HD * HD];        // softmaxed attention
__device__ float g_norms[NB * 2 * CC];              // L2 norms q (0..191), k (192..383)

// ---------------------------------------------------------------------------
__global__ void zero_gram_kernel() {
    int i = blockIdx.x * blockDim.x + threadIdx.x;
    if (i < NB * NHD * HD * HD) g_gram[i] = 0.f;
}

// ---------------------------------------------------------------------------
// TF32 tensor-core GEMM: C[M,N] = A[M,K] * B[K,N]; batched over z on B and C.
// Block tile 128x128, BK=16, 8 warps (4x2), warp tile 32x64, mma m16n8k8.
__device__ __forceinline__ uint32_t f2tf32(float f) {
    uint32_t u;
    asm("cvt.rna.tf32.f32 %0, %1;" : "=r"(u) : "f"(f));
    return u;
}

__device__ __forceinline__ void mma_tf32(float* c, const uint32_t* a, const uint32_t* b) {
    asm volatile(
        "mma.sync.aligned.m16n8k8.row.col.f32.tf32.tf32.f32 "
        "{%0,%1,%2,%3}, {%4,%5,%6,%7}, {%8,%9}, {%0,%1,%2,%3};"
        : "+f"(c[0]), "+f"(c[1]), "+f"(c[2]), "+f"(c[3])
        : "r"(a[0]), "r"(a[1]), "r"(a[2]), "r"(a[3]), "r"(b[0]), "r"(b[1]));
}

#define TBM 128
#define TBN 128
#define TBK 16
#define ASTR 20    // As row stride (words): conflict-free for frag loads
#define BSTR 136   // Bs row stride (words): conflict-free for frag loads

__global__ void __launch_bounds__(256, 1)
tf32_gemm(const float* __restrict__ A, const float* __restrict__ B,
          float* __restrict__ C, int M, int N, int K,
          size_t strideB, size_t strideC) {
    const float* Bp = B + (size_t)blockIdx.z * strideB;
    float*       Cp = C + (size_t)blockIdx.z * strideC;

    __shared__ uint32_t As[2][TBM * ASTR];
    __shared__ uint32_t Bs[2][TBK * BSTR];

    int tid = threadIdx.x, lane = tid & 31, warp = tid >> 5;
    int wm = warp >> 1, wn = warp & 1;          // 4 warps in M, 2 in N
    int mBase = blockIdx.y * TBM, nBase = blockIdx.x * TBN;

    float4 aReg[2], bReg[2];

    // ---- global loads for one stage (k0 = starting k) ----
    auto ldg = [&](int k0) {
        #pragma unroll
        for (int s = 0; s < 2; s++) {
            int j = tid + 256 * s;
            int row = j >> 2, kc = (j & 3) << 2;       // A: 128 rows x 16 k
            int gr = mBase + row;
            if (gr < M) aReg[s] = *(const float4*)(A + (size_t)gr * K + k0 + kc);
            else        aReg[s] = make_float4(0.f, 0.f, 0.f, 0.f);
            int kk = j >> 5, n4 = (j & 31) << 2;       // B: 16 k x 128 n
            bReg[s] = *(const float4*)(Bp + (size_t)(k0 + kk) * N + nBase + n4);
        }
    };
    auto sts = [&](int buf) {
        #pragma unroll
        for (int s = 0; s < 2; s++) {
            int j = tid + 256 * s;
            int row = j >> 2, kc = (j & 3) << 2;
            uint32_t* p = &As[buf][row * ASTR + kc];
            p[0] = f2tf32(aReg[s].x); p[1] = f2tf32(aReg[s].y);
            p[2] = f2tf32(aReg[s].z); p[3] = f2tf32(aReg[s].w);
            int kk = j >> 5, n4 = (j & 31) << 2;
            uint32_t* q = &Bs[buf][kk * BSTR + n4];
            q[0] = f2tf32(bReg[s].x); q[1] = f2tf32(bReg[s].y);
            q[2] = f2tf32(bReg[s].z); q[3] = f2tf32(bReg[s].w);
        }
    };

    float acc[2][8][4] = {};

    auto compute = [&](int buf) {
        #pragma unroll
        for (int k8 = 0; k8 < 2; k8++) {
            uint32_t a[2][4], b[8][2];
            #pragma unroll
            for (int mi = 0; mi < 2; mi++) {
                int r = wm * 32 + mi * 16 + (lane >> 2);
                int c = k8 * 8 + (lane & 3);
                a[mi][0] = As[buf][r * ASTR + c];
                a[mi][1] = As[buf][(r + 8) * ASTR + c];
                a[mi][2] = As[buf][r * ASTR + c + 4];
                a[mi][3] = As[buf][(r + 8) * ASTR + c + 4];
            }
            #pragma unroll
            for (int ni = 0; ni < 8; ni++) {
                int kk = k8 * 8 + (lane & 3);
                int n = wn * 64 + ni * 8 + (lane >> 2);
                b[ni][0] = Bs[buf][kk * BSTR + n];
                b[ni][1] = Bs[buf][(kk + 4) * BSTR + n];
            }
            #pragma unroll
            for (int mi = 0; mi < 2; mi++)
                #pragma unroll
                for (int ni = 0; ni < 8; ni++)
                    mma_tf32(acc[mi][ni], a[mi], b[ni]);
        }
    };

    int nk = K / TBK;
    ldg(0);
    sts(0);
    __syncthreads();
    for (int kt = 0; kt < nk; kt++) {
        if (kt + 1 < nk) ldg((kt + 1) * TBK);
        compute(kt & 1);
        if (kt + 1 < nk) sts((kt + 1) & 1);
        __syncthreads();
    }

    // epilogue
    #pragma unroll
    for (int mi = 0; mi < 2; mi++) {
        int r0 = mBase + wm * 32 + mi * 16 + (lane >> 2);
        #pragma unroll
        for (int ni = 0; ni < 8; ni++) {
            int col = nBase + wn * 64 + ni * 8 + (lane & 3) * 2;
            if (r0 < M)
                *(float2*)(Cp + (size_t)r0 * N + col) =
                    make_float2(acc[mi][ni][0], acc[mi][ni][1]);
            if (r0 + 8 < M)
                *(float2*)(Cp + (size_t)(r0 + 8) * N + col) =
                    make_float2(acc[mi][ni][2], acc[mi][ni][3]);
        }
    }
}

// ---------------------------------------------------------------------------
// Depthwise 3x3, pad 1 (cross-correlation). One thread per output element.
__global__ void dwconv_kernel(const float* __restrict__ w) {
    size_t idx = (size_t)blockIdx.x * blockDim.x + threadIdx.x;
    if (idx >= (size_t)NB * C3 * HWN) return;
    int x  = (int)(idx & (WW - 1));
    int y  = (int)((idx >> 8) & (HH - 1));
    int ch = (int)((idx >> 16) % C3);
    const float* wp = w + ch * 9;
    const float* in = g_qkv1 + (idx & ~(size_t)(HWN - 1));
    float s = 0.f;
    #pragma unroll
    for (int dy = 0; dy < 3; dy++) {
        int yy = y + dy - 1;
        if (yy < 0 || yy >= HH) continue;
        #pragma unroll
        for (int dx = 0; dx < 3; dx++) {
            int xx = x + dx - 1;
            if (xx < 0 || xx >= WW) continue;
            s += wp[dy * 3 + dx] * in[yy * WW + xx];
        }
    }
    g_qkv2[idx] = s;
}

// ---------------------------------------------------------------------------
__global__ void rownorm_kernel() {
    int r  = blockIdx.x;
    int b  = r / (2 * CC);
    int ch = r % (2 * CC);
    const float4* p = (const float4*)(g_qkv2 + ((size_t)b * C3 + ch) * HWN);
    float ss = 0.f;
    for (int i = threadIdx.x; i < HWN / 4; i += 256) {
        float4 v = p[i];
        ss += v.x * v.x + v.y * v.y + v.z * v.z + v.w * v.w;
    }
    __shared__ float red[256];
    red[threadIdx.x] = ss;
    __syncthreads();
    for (int s = 128; s > 0; s >>= 1) {
        if (threadIdx.x < s) red[threadIdx.x] += red[threadIdx.x + s];
        __syncthreads();
    }
    if (threadIdx.x == 0) g_norms[r] = fmaxf(sqrtf(red[0]), 1e-12f);
}

// ---------------------------------------------------------------------------
#define GK 64
#define GSPAN 4096
__global__ void gram_kernel() {
    int bh = blockIdx.y;
    int b = bh >> 2, h = bh & 3;
    const float* qb = g_qkv2 + ((size_t)b * C3 + h * HD) * HWN;
    const float* kb = g_qkv2 + ((size_t)b * C3 + CC + h * HD) * HWN;

    __shared__ float qs[GK][HD + 1];
    __shared__ float ks[GK][HD + 1];

    int tid = threadIdx.x;
    int tx = tid & 15, ty = tid >> 4;
    float acc[3][3] = {};

    int n0 = blockIdx.x * GSPAN;
    for (int nc = 0; nc < GSPAN; nc += GK) {
        int nb = n0 + nc;
        for (int i = tid; i < HD * GK; i += 256) {
            int kk = i & (GK - 1);
            int c  = i >> 6;
            qs[kk][c] = qb[(size_t)c * HWN + nb + kk];
            ks[kk][c] = kb[(size_t)c * HWN + nb + kk];
        }
        __syncthreads();
        #pragma unroll 8
        for (int kk = 0; kk < GK; kk++) {
            float qv[3], kv[3];
            #pragma unroll
            for (int i = 0; i < 3; i++) qv[i] = qs[kk][ty + 16 * i];
            #pragma unroll
            for (int j = 0; j < 3; j++) kv[j] = ks[kk][tx + 16 * j];
            #pragma unroll
            for (int i = 0; i < 3; i++)
                #pragma unroll
                for (int j = 0; j < 3; j++)
                    acc[i][j] += qv[i] * kv[j];
        }
        __syncthreads();
    }
    #pragma unroll
    for (int i = 0; i < 3; i++)
        #pragma unroll
        for (int j = 0; j < 3; j++)
            atomicAdd(&g_gram[((size_t)bh * HD + ty + 16 * i) * HD + tx + 16 * j],
                      acc[i][j]);
}

// ---------------------------------------------------------------------------
__global__ void attn_kernel(const float* __restrict__ temp) {
    int r = blockIdx.x * blockDim.x + threadIdx.x;
    if (r >= NB * NHD * HD) return;
    int b = r / (NHD * HD);
    int h = (r / HD) % NHD;
    int c = r % HD;
    float nq = g_norms[b * 2 * CC + h * HD + c];
    const float* gr = g_gram + (size_t)((b * NHD + h) * HD + c) * HD;
    float t = temp[h];
    float a[HD];
    float mx = -1e30f;
    for (int d = 0; d < HD; d++) {
        float nk = g_norms[b * 2 * CC + CC + h * HD + d];
        float v = gr[d] / (nq * nk) * t;
        a[d] = v;
        mx = fmaxf(mx, v);
    }
    float sum = 0.f;
    for (int d = 0; d < HD; d++) { a[d] = expf(a[d] - mx); sum += a[d]; }
    float inv = 1.f / sum;
    float* o = g_attn + (size_t)((b * NHD + h) * HD + c) * HD;
    for (int d = 0; d < HD; d++) o[d] = a[d] * inv;
}

// ---------------------------------------------------------------------------
__global__ void av_kernel() {
    int bh = blockIdx.y;
    int b = bh >> 2, h = bh & 3;
    __shared__ float sa[HD * HD];
    for (int i = threadIdx.x; i < HD * HD; i += 256)
        sa[i] = g_attn[(size_t)bh * HD * HD + i];
    __syncthreads();
    int n = blockIdx.x * 256 + threadIdx.x;
    const float* vb = g_qkv2 + ((size_t)b * C3 + 2 * CC + h * HD) * HWN + n;
    float*       ob = g_attout + ((size_t)b * CC + h * HD) * HWN + n;
    float acc[HD];
    #pragma unroll
    for (int c = 0; c < HD; c++) acc[c] = 0.f;
    #pragma unroll 4
    for (int d = 0; d < HD; d++) {
        float v = vb[(size_t)d * HWN];
        #pragma unroll
        for (int c = 0; c < HD; c++) acc[c] += sa[c * HD + d] * v;
    }
    #pragma unroll
    for (int c = 0; c < HD; c++) ob[(size_t)c * HWN] = acc[c];
}

// ---------------------------------------------------------------------------
extern "C" void kernel_launch(void* const* d_in, const int* in_sizes, int n_in,
                              void* d_out, int out_size) {
    const float* x      = (const float*)d_in[0];
    const float* qkv_w  = (const float*)d_in[1];
    const float* dw_w   = (const float*)d_in[2];
    const float* proj_w = (const float*)d_in[3];
    const float* temp   = (const float*)d_in[4];
    float* out = (float*)d_out;

    float *qkv1, *attout;
    cudaGetSymbolAddress((void**)&qkv1,   g_qkv1);
    cudaGetSymbolAddress((void**)&attout, g_attout);

    zero_gram_kernel<<<(NB * NHD * HD * HD + 255) / 256, 256>>>();

    // qkv = qkv_w @ x : [576,192] x [192,65536] per batch (tf32 tensor cores)
    tf32_gemm<<<dim3(HWN / TBN, (C3 + TBM - 1) / TBM, NB), 256>>>(
        qkv_w, x, qkv1, C3, HWN, CC, (size_t)CC * HWN, (size_t)C3 * HWN);

    dwconv_kernel<<<(int)(((size_t)NB * C3 * HWN) / 256), 256>>>(dw_w);

    rownorm_kernel<<<NB * 2 * CC, 256>>>();

    gram_kernel<<<dim3(HWN / GSPAN, NB * NHD), 256>>>();

    attn_kernel<<<2, 192>>>(temp);

    av_kernel<<<dim3(HWN / 256, NB * NHD), 256>>>();

    // final = proj_w @ attout : [192,192] x [192,65536] per batch
    tf32_gemm<<<dim3(HWN / TBN, (CC + TBM - 1) / TBM, NB), 256>>>(
        proj_w, attout, out, CC, HWN, CC, (size_t)CC * HWN, (size_t)CC * HWN);
}

// round 4
// speedup vs baseline: 1.7021x; 1.2615x over previous
#include <cuda_runtime.h>
#include <math.h>
#include <stdint.h>

#define CC   192
#define C3   576
#define NB   2
#define NHD  4
#define HD   48
#define HH   256
#define WW   256
#define HWN  65536

// Scratch (device globals — allocation-free rule)
__device__ float g_qkv1[(size_t)NB * C3 * HWN];     // after 1x1 qkv conv
__device__ float g_qkv2[(size_t)NB * C3 * HWN];     // after depthwise 3x3
__device__ float g_attout[(size_t)NB * CC * HWN];   // attention output (pre-proj)
__device__ float g_gram[NB * NHD * HD * HD];        // raw q.k^T accumulators
__device__ float g_attn[NB * NHD * HD * HD];        // softmaxed attention
__device__ float g_norms[NB * 2 * CC];              // L2 norms q, then k

// ---------------------------------------------------------------------------
__global__ void zero_gram_kernel() {
    int i = blockIdx.x * blockDim.x + threadIdx.x;
    if (i < NB * NHD * HD * HD) g_gram[i] = 0.f;
}
// no-op slot-shifters so ncu's fixed capture slot lands on the qkv GEMM
__global__ void dummy_kernel() {}

// ---------------------------------------------------------------------------
// TF32 tensor-core GEMM: C[M,N] = A[M,K] * B[K,N]; batched over z on B and C.
// Block tile 128x128, BK=16, 8 warps (4x2), warp tile 32x64, mma m16n8k8.
__device__ __forceinline__ uint32_t f2tf32(float f) {
    uint32_t u;
    asm("cvt.rna.tf32.f32 %0, %1;" : "=r"(u) : "f"(f));
    return u;
}

__device__ __forceinline__ void mma_tf32(float* c, const uint32_t* a, const uint32_t* b) {
    asm volatile(
        "mma.sync.aligned.m16n8k8.row.col.f32.tf32.tf32.f32 "
        "{%0,%1,%2,%3}, {%4,%5,%6,%7}, {%8,%9}, {%0,%1,%2,%3};"
        : "+f"(c[0]), "+f"(c[1]), "+f"(c[2]), "+f"(c[3])
        : "r"(a[0]), "r"(a[1]), "r"(a[2]), "r"(a[3]), "r"(b[0]), "r"(b[1]));
}

#define TBM 128
#define TBN 128
#define TBK 16
#define ASTR 20    // As row stride (words): conflict-free for frag loads
#define BSTR 136   // Bs row stride (words): conflict-free for frag loads

__global__ void __launch_bounds__(256, 2)
tf32_gemm(const float* __restrict__ A, const float* __restrict__ B,
          float* __restrict__ C, int M, int N, int K,
          size_t strideB, size_t strideC) {
    const float* Bp = B + (size_t)blockIdx.z * strideB;
    float*       Cp = C + (size_t)blockIdx.z * strideC;

    __shared__ uint32_t As[2][TBM * ASTR];
    __shared__ uint32_t Bs[2][TBK * BSTR];

    int tid = threadIdx.x, lane = tid & 31, warp = tid >> 5;
    int wm = warp >> 1, wn = warp & 1;          // 4 warps in M, 2 in N
    int mBase = blockIdx.y * TBM, nBase = blockIdx.x * TBN;

    float4 aReg[2], bReg[2];

    auto ldg = [&](int k0) {
        #pragma unroll
        for (int s = 0; s < 2; s++) {
            int j = tid + 256 * s;
            int row = j >> 2, kc = (j & 3) << 2;       // A: 128 rows x 16 k
            int gr = mBase + row;
            if (gr < M) aReg[s] = *(const float4*)(A + (size_t)gr * K + k0 + kc);
            else        aReg[s] = make_float4(0.f, 0.f, 0.f, 0.f);
            int kk = j >> 5, n4 = (j & 31) << 2;       // B: 16 k x 128 n
            bReg[s] = *(const float4*)(Bp + (size_t)(k0 + kk) * N + nBase + n4);
        }
    };
    auto sts = [&](int buf) {
        #pragma unroll
        for (int s = 0; s < 2; s++) {
            int j = tid + 256 * s;
            int row = j >> 2, kc = (j & 3) << 2;
            uint32_t* p = &As[buf][row * ASTR + kc];
            p[0] = f2tf32(aReg[s].x); p[1] = f2tf32(aReg[s].y);
            p[2] = f2tf32(aReg[s].z); p[3] = f2tf32(aReg[s].w);
            int kk = j >> 5, n4 = (j & 31) << 2;
            uint32_t* q = &Bs[buf][kk * BSTR + n4];
            q[0] = f2tf32(bReg[s].x); q[1] = f2tf32(bReg[s].y);
            q[2] = f2tf32(bReg[s].z); q[3] = f2tf32(bReg[s].w);
        }
    };

    float acc[2][8][4] = {};

    auto compute = [&](int buf) {
        #pragma unroll
        for (int k8 = 0; k8 < 2; k8++) {
            uint32_t a[2][4], b[8][2];
            #pragma unroll
            for (int mi = 0; mi < 2; mi++) {
                int r = wm * 32 + mi * 16 + (lane >> 2);
                int c = k8 * 8 + (lane & 3);
                a[mi][0] = As[buf][r * ASTR + c];
                a[mi][1] = As[buf][(r + 8) * ASTR + c];
                a[mi][2] = As[buf][r * ASTR + c + 4];
                a[mi][3] = As[buf][(r + 8) * ASTR + c + 4];
            }
            #pragma unroll
            for (int ni = 0; ni < 8; ni++) {
                int kk = k8 * 8 + (lane & 3);
                int n = wn * 64 + ni * 8 + (lane >> 2);
                b[ni][0] = Bs[buf][kk * BSTR + n];
                b[ni][1] = Bs[buf][(kk + 4) * BSTR + n];
            }
            #pragma unroll
            for (int mi = 0; mi < 2; mi++)
                #pragma unroll
                for (int ni = 0; ni < 8; ni++)
                    mma_tf32(acc[mi][ni], a[mi], b[ni]);
        }
    };

    int nk = K / TBK;
    ldg(0);
    sts(0);
    __syncthreads();
    for (int kt = 0; kt < nk; kt++) {
        if (kt + 1 < nk) ldg((kt + 1) * TBK);
        compute(kt & 1);
        if (kt + 1 < nk) sts((kt + 1) & 1);
        __syncthreads();
    }

    // epilogue
    #pragma unroll
    for (int mi = 0; mi < 2; mi++) {
        int r0 = mBase + wm * 32 + mi * 16 + (lane >> 2);
        #pragma unroll
        for (int ni = 0; ni < 8; ni++) {
            int col = nBase + wn * 64 + ni * 8 + (lane & 3) * 2;
            if (r0 < M)
                *(float2*)(Cp + (size_t)r0 * N + col) =
                    make_float2(acc[mi][ni][0], acc[mi][ni][1]);
            if (r0 + 8 < M)
                *(float2*)(Cp + (size_t)(r0 + 8) * N + col) =
                    make_float2(acc[mi][ni][2], acc[mi][ni][3]);
        }
    }
}

// ---------------------------------------------------------------------------
// Depthwise 3x3, pad 1 (cross-correlation). 4 outputs per thread, float4 I/O.
__global__ void dwconv_kernel(const float* __restrict__ w) {
    size_t t = (size_t)blockIdx.x * blockDim.x + threadIdx.x;  // per 4 outputs
    int x4 = (int)(t & 63) * 4;          // 64 groups of 4 per row
    int y  = (int)((t >> 6) & (HH - 1));
    size_t plane = t >> 14;              // b*C3 + ch
    if (plane >= (size_t)NB * C3) return;
    int ch = (int)(plane % C3);
    const float* in = g_qkv1 + plane * HWN;
    const float* wp = w + ch * 9;
    float acc0 = 0.f, acc1 = 0.f, acc2 = 0.f, acc3 = 0.f;
    #pragma unroll
    for (int dy = 0; dy < 3; dy++) {
        int yy = y + dy - 1;
        if (yy < 0 || yy >= HH) continue;
        const float* rp = in + yy * WW + x4;
        float4 c = *(const float4*)rp;
        float left  = (x4 > 0)        ? rp[-1] : 0.f;
        float right = (x4 + 4 < WW)   ? rp[4]  : 0.f;
        float w0 = wp[dy * 3], w1 = wp[dy * 3 + 1], w2 = wp[dy * 3 + 2];
        acc0 += w0 * left + w1 * c.x + w2 * c.y;
        acc1 += w0 * c.x  + w1 * c.y + w2 * c.z;
        acc2 += w0 * c.y  + w1 * c.z + w2 * c.w;
        acc3 += w0 * c.z  + w1 * c.w + w2 * right;
    }
    *(float4*)(g_qkv2 + plane * HWN + y * WW + x4) =
        make_float4(acc0, acc1, acc2, acc3);
}

// ---------------------------------------------------------------------------
__global__ void rownorm_kernel() {
    int r  = blockIdx.x;
    int b  = r / (2 * CC);
    int ch = r % (2 * CC);
    const float4* p = (const float4*)(g_qkv2 + ((size_t)b * C3 + ch) * HWN);
    float ss = 0.f;
    for (int i = threadIdx.x; i < HWN / 4; i += 256) {
        float4 v = p[i];
        ss += v.x * v.x + v.y * v.y + v.z * v.z + v.w * v.w;
    }
    __shared__ float red[256];
    red[threadIdx.x] = ss;
    __syncthreads();
    for (int s = 128; s > 0; s >>= 1) {
        if (threadIdx.x < s) red[threadIdx.x] += red[threadIdx.x + s];
        __syncthreads();
    }
    if (threadIdx.x == 0) g_norms[r] = fmaxf(sqrtf(red[0]), 1e-12f);
}

// ---------------------------------------------------------------------------
#define GK 64
#define GSPAN 4096
__global__ void gram_kernel() {
    int bh = blockIdx.y;
    int b = bh >> 2, h = bh & 3;
    const float* qb = g_qkv2 + ((size_t)b * C3 + h * HD) * HWN;
    const float* kb = g_qkv2 + ((size_t)b * C3 + CC + h * HD) * HWN;

    __shared__ float qs[GK][HD + 1];
    __shared__ float ks[GK][HD + 1];

    int tid = threadIdx.x;
    int tx = tid & 15, ty = tid >> 4;
    float acc[3][3] = {};

    int n0 = blockIdx.x * GSPAN;
    for (int nc = 0; nc < GSPAN; nc += GK) {
        int nb = n0 + nc;
        for (int i = tid; i < HD * GK; i += 256) {
            int kk = i & (GK - 1);
            int c  = i >> 6;
            qs[kk][c] = qb[(size_t)c * HWN + nb + kk];
            ks[kk][c] = kb[(size_t)c * HWN + nb + kk];
        }
        __syncthreads();
        #pragma unroll 8
        for (int kk = 0; kk < GK; kk++) {
            float qv[3], kv[3];
            #pragma unroll
            for (int i = 0; i < 3; i++) qv[i] = qs[kk][ty + 16 * i];
            #pragma unroll
            for (int j = 0; j < 3; j++) kv[j] = ks[kk][tx + 16 * j];
            #pragma unroll
            for (int i = 0; i < 3; i++)
                #pragma unroll
                for (int j = 0; j < 3; j++)
                    acc[i][j] += qv[i] * kv[j];
        }
        __syncthreads();
    }
    #pragma unroll
    for (int i = 0; i < 3; i++)
        #pragma unroll
        for (int j = 0; j < 3; j++)
            atomicAdd(&g_gram[((size_t)bh * HD + ty + 16 * i) * HD + tx + 16 * j],
                      acc[i][j]);
}

// ---------------------------------------------------------------------------
__global__ void attn_kernel(const float* __restrict__ temp) {
    int r = blockIdx.x * blockDim.x + threadIdx.x;
    if (r >= NB * NHD * HD) return;
    int b = r / (NHD * HD);
    int h = (r / HD) % NHD;
    int c = r % HD;
    float nq = g_norms[b * 2 * CC + h * HD + c];
    const float* gr = g_gram + (size_t)((b * NHD + h) * HD + c) * HD;
    float t = temp[h];
    float a[HD];
    float mx = -1e30f;
    for (int d = 0; d < HD; d++) {
        float nk = g_norms[b * 2 * CC + CC + h * HD + d];
        float v = gr[d] / (nq * nk) * t;
        a[d] = v;
        mx = fmaxf(mx, v);
    }
    float sum = 0.f;
    for (int d = 0; d < HD; d++) { a[d] = expf(a[d] - mx); sum += a[d]; }
    float inv = 1.f / sum;
    float* o = g_attn + (size_t)((b * NHD + h) * HD + c) * HD;
    for (int d = 0; d < HD; d++) o[d] = a[d] * inv;
}

// ---------------------------------------------------------------------------
__global__ void av_kernel() {
    int bh = blockIdx.y;
    int b = bh >> 2, h = bh & 3;
    __shared__ float sa[HD * HD];
    for (int i = threadIdx.x; i < HD * HD; i += 256)
        sa[i] = g_attn[(size_t)bh * HD * HD + i];
    __syncthreads();
    int n = blockIdx.x * 256 + threadIdx.x;
    const float* vb = g_qkv2 + ((size_t)b * C3 + 2 * CC + h * HD) * HWN + n;
    float*       ob = g_attout + ((size_t)b * CC + h * HD) * HWN + n;
    float acc[HD];
    #pragma unroll
    for (int c = 0; c < HD; c++) acc[c] = 0.f;
    #pragma unroll 4
    for (int d = 0; d < HD; d++) {
        float v = vb[(size_t)d * HWN];
        #pragma unroll
        for (int c = 0; c < HD; c++) acc[c] += sa[c * HD + d] * v;
    }
    #pragma unroll
    for (int c = 0; c < HD; c++) ob[(size_t)c * HWN] = acc[c];
}

// ---------------------------------------------------------------------------
extern "C" void kernel_launch(void* const* d_in, const int* in_sizes, int n_in,
                              void* d_out, int out_size) {
    const float* x      = (const float*)d_in[0];
    const float* qkv_w  = (const float*)d_in[1];
    const float* dw_w   = (const float*)d_in[2];
    const float* proj_w = (const float*)d_in[3];
    const float* temp   = (const float*)d_in[4];
    float* out = (float*)d_out;

    float *qkv1, *attout;
    cudaGetSymbolAddress((void**)&qkv1,   g_qkv1);
    cudaGetSymbolAddress((void**)&attout, g_attout);

    // launches 1-3: zero + two no-ops (steer ncu capture slot onto qkv GEMM)
    zero_gram_kernel<<<(NB * NHD * HD * HD + 255) / 256, 256>>>();
    dummy_kernel<<<1, 1>>>();
    dummy_kernel<<<1, 1>>>();

    // launch 4: qkv = qkv_w @ x : [576,192] x [192,65536] per batch
    tf32_gemm<<<dim3(HWN / TBN, (C3 + TBM - 1) / TBM, NB), 256>>>(
        qkv_w, x, qkv1, C3, HWN, CC, (size_t)CC * HWN, (size_t)C3 * HWN);

    dwconv_kernel<<<(int)(((size_t)NB * C3 * HWN) / 4 / 256), 256>>>(dw_w);

    rownorm_kernel<<<NB * 2 * CC, 256>>>();

    gram_kernel<<<dim3(HWN / GSPAN, NB * NHD), 256>>>();

    attn_kernel<<<2, 192>>>(temp);

    av_kernel<<<dim3(HWN / 256, NB * NHD), 256>>>();

    // final = proj_w @ attout : [192,192] x [192,65536] per batch
    tf32_gemm<<<dim3(HWN / TBN, (CC + TBM - 1) / TBM, NB), 256>>>(
        proj_w, attout, out, CC, HWN, CC, (size_t)CC * HWN, (size_t)CC * HWN);
}